// round 1
// baseline (speedup 1.0000x reference)
#include <cuda_runtime.h>

// GRU last-hidden: B=16384, T=512, I=4, H=64. Each thread owns one batch
// element; weights in smem; h in registers (refreshed from a thread-private
// smem column each step to avoid dynamic register indexing).

#define NB   16384
#define TT   512
#define II   4
#define HH   64
#define GG   192          // 3*H
#define NT   128          // threads per block

// smem layout (floats):
//   sW    [GG*HH]  = 12288   (w_hh, row-major [j][k])
//   sWih  [GG*II]  =   768   (w_ih, row-major [j][i])
//   sBih  [GG]     =   192
//   sBhh  [GG]     =   192
//   hs    [HH*NT]  =  8192   (per-thread hidden state column, [k][tid])
#define SMEM_FLOATS (GG*HH + GG*II + GG + GG + HH*NT)

__device__ __forceinline__ float sigmoidf_(float x) {
    return __fdividef(1.0f, 1.0f + __expf(-x));
}
__device__ __forceinline__ float tanhf_(float x) {
    // tanh(x) = 1 - 2/(e^{2x}+1); large |x| saturates correctly via expf inf/0.
    return 1.0f - __fdividef(2.0f, __expf(2.0f * x) + 1.0f);
}

extern __shared__ float smem_[];

__global__ void __launch_bounds__(NT, 1) gru_kernel(
    const float* __restrict__ x,      // [B, T, I]
    const float* __restrict__ w_ih,   // [3H, I]
    const float* __restrict__ w_hh,   // [3H, H]
    const float* __restrict__ b_ih,   // [3H]
    const float* __restrict__ b_hh,   // [3H]
    float* __restrict__ out)          // [B, H]
{
    float* sW   = smem_;
    float* sWih = sW   + GG * HH;
    float* sBih = sWih + GG * II;
    float* sBhh = sBih + GG;
    float* hs   = sBhh + GG;

    const int tid = threadIdx.x;

    for (int i = tid; i < GG * HH; i += NT) sW[i]   = w_hh[i];
    for (int i = tid; i < GG * II; i += NT) sWih[i] = w_ih[i];
    for (int i = tid; i < GG;      i += NT) { sBih[i] = b_ih[i]; sBhh[i] = b_hh[i]; }
    #pragma unroll
    for (int k = 0; k < HH; ++k) hs[k * NT + tid] = 0.0f;
    __syncthreads();

    const int b = blockIdx.x * NT + tid;
    const float4* __restrict__ xp =
        reinterpret_cast<const float4*>(x + (size_t)b * (TT * II));

    float h[HH];

    for (int t = 0; t < TT; ++t) {
        const float4 xv = __ldg(&xp[t]);

        // refresh register copy of h from the thread-private smem column
        #pragma unroll
        for (int k = 0; k < HH; ++k) h[k] = hs[k * NT + tid];

        #pragma unroll 2
        for (int j = 0; j < HH; ++j) {
            const float4* wr = reinterpret_cast<const float4*>(sW + (size_t)j * HH);
            const float4* wz = reinterpret_cast<const float4*>(sW + (size_t)(j + HH) * HH);
            const float4* wn = reinterpret_cast<const float4*>(sW + (size_t)(j + 2 * HH) * HH);

            float r0 = 0.f, r1 = 0.f, r2 = 0.f, r3 = 0.f;
            float z0 = 0.f, z1 = 0.f, z2 = 0.f, z3 = 0.f;
            float n0 = 0.f, n1 = 0.f, n2 = 0.f, n3 = 0.f;
            #pragma unroll
            for (int k = 0; k < HH / 4; ++k) {
                const float4 a = wr[k];
                const float4 c = wz[k];
                const float4 d = wn[k];
                const float h0 = h[4*k+0], h1 = h[4*k+1];
                const float h2 = h[4*k+2], h3 = h[4*k+3];
                r0 += a.x * h0;  r1 += a.y * h1;  r2 += a.z * h2;  r3 += a.w * h3;
                z0 += c.x * h0;  z1 += c.y * h1;  z2 += c.z * h2;  z3 += c.w * h3;
                n0 += d.x * h0;  n1 += d.y * h1;  n2 += d.z * h2;  n3 += d.w * h3;
            }
            const float hr = (r0 + r1) + (r2 + r3) + sBhh[j];
            const float hz = (z0 + z1) + (z2 + z3) + sBhh[j + HH];
            const float hn = (n0 + n1) + (n2 + n3) + sBhh[j + 2 * HH];

            const float4 wiR = reinterpret_cast<const float4*>(sWih)[j];
            const float4 wiZ = reinterpret_cast<const float4*>(sWih)[j + HH];
            const float4 wiN = reinterpret_cast<const float4*>(sWih)[j + 2 * HH];
            const float xr = sBih[j]          + wiR.x*xv.x + wiR.y*xv.y + wiR.z*xv.z + wiR.w*xv.w;
            const float xz = sBih[j + HH]     + wiZ.x*xv.x + wiZ.y*xv.y + wiZ.z*xv.z + wiZ.w*xv.w;
            const float xn = sBih[j + 2 * HH] + wiN.x*xv.x + wiN.y*xv.y + wiN.z*xv.z + wiN.w*xv.w;

            const float rg = sigmoidf_(xr + hr);
            const float zg = sigmoidf_(xz + hz);
            const float ng = tanhf_(xn + rg * hn);

            const float ho = hs[j * NT + tid];        // old h_j (smem copy)
            hs[j * NT + tid] = (1.0f - zg) * ng + zg * ho;
        }
    }

    #pragma unroll
    for (int k = 0; k < HH; ++k)
        out[(size_t)b * HH + k] = hs[k * NT + tid];
}

extern "C" void kernel_launch(void* const* d_in, const int* in_sizes, int n_in,
                              void* d_out, int out_size) {
    const float* x    = (const float*)d_in[0];
    const float* w_ih = (const float*)d_in[1];
    const float* w_hh = (const float*)d_in[2];
    const float* b_ih = (const float*)d_in[3];
    const float* b_hh = (const float*)d_in[4];
    float* out = (float*)d_out;

    const int smem_bytes = SMEM_FLOATS * (int)sizeof(float);  // 86528
    cudaFuncSetAttribute(gru_kernel, cudaFuncAttributeMaxDynamicSharedMemorySize,
                         smem_bytes);
    gru_kernel<<<NB / NT, NT, smem_bytes>>>(x, w_ih, w_hh, b_ih, b_hh, out);
}

// round 2
// speedup vs baseline: 1.0777x; 1.0777x over previous
#include <cuda_runtime.h>

// GRU last-hidden: B=16384, T=512, I=4, H=64.
// One thread per batch element. Dot products computed with packed
// fma.rn.f32x2 along the K dimension: h kept as 32 f32x2 pairs, w_hh rows
// are K-contiguous so LDS.128 delivers two packed weight pairs directly.

#define NB   16384
#define TT   512
#define II   4
#define HH   64
#define HP   32           // H/2 packed pairs
#define GG   192          // 3*H
#define NT   128          // threads per block

typedef unsigned long long u64;

// smem layout (bytes):
//   hs    [HP * NT] u64  = 32768   (per-thread hidden state, packed pairs)
//   sW    [GG * HH] f32  = 49152   (w_hh, row-major [j][k])
//   sWih  [GG * II] f32  =  3072
//   sBih  [GG] f32       =   768
//   sBhh  [GG] f32       =   768
#define SMEM_BYTES (HP*NT*8 + GG*HH*4 + GG*II*4 + GG*4 + GG*4)

__device__ __forceinline__ u64 fma2(u64 a, u64 b, u64 c) {
    u64 d; asm("fma.rn.f32x2 %0, %1, %2, %3;" : "=l"(d) : "l"(a), "l"(b), "l"(c));
    return d;
}
__device__ __forceinline__ u64 mul2(u64 a, u64 b) {
    u64 d; asm("mul.rn.f32x2 %0, %1, %2;" : "=l"(d) : "l"(a), "l"(b));
    return d;
}
__device__ __forceinline__ u64 add2(u64 a, u64 b) {
    u64 d; asm("add.rn.f32x2 %0, %1, %2;" : "=l"(d) : "l"(a), "l"(b));
    return d;
}
__device__ __forceinline__ float hsum2(u64 a) {
    float l, h; asm("mov.b64 {%0, %1}, %2;" : "=f"(l), "=f"(h) : "l"(a));
    return l + h;
}
__device__ __forceinline__ u64 pack2(float l, float h) {
    u64 d; asm("mov.b64 %0, {%1, %2};" : "=l"(d) : "f"(l), "f"(h));
    return d;
}

__device__ __forceinline__ float sigmoidf_(float x) {
    return __fdividef(1.0f, 1.0f + __expf(-x));
}
__device__ __forceinline__ float tanhf_(float x) {
    return 1.0f - __fdividef(2.0f, __expf(2.0f * x) + 1.0f);
}

extern __shared__ char smem_[];

__global__ void __launch_bounds__(NT, 1) gru_kernel(
    const float* __restrict__ x,      // [B, T, I]
    const float* __restrict__ w_ih,   // [3H, I]
    const float* __restrict__ w_hh,   // [3H, H]
    const float* __restrict__ b_ih,   // [3H]
    const float* __restrict__ b_hh,   // [3H]
    float* __restrict__ out)          // [B, H]
{
    u64*   hs   = reinterpret_cast<u64*>(smem_);                 // 8B aligned
    float* sW   = reinterpret_cast<float*>(smem_ + HP * NT * 8);
    float* sWih = sW   + GG * HH;
    float* sBih = sWih + GG * II;
    float* sBhh = sBih + GG;

    const int tid = threadIdx.x;

    for (int i = tid; i < GG * HH; i += NT) sW[i]   = w_hh[i];
    for (int i = tid; i < GG * II; i += NT) sWih[i] = w_ih[i];
    for (int i = tid; i < GG;      i += NT) { sBih[i] = b_ih[i]; sBhh[i] = b_hh[i]; }
    #pragma unroll
    for (int kp = 0; kp < HP; ++kp) hs[kp * NT + tid] = 0ULL;
    __syncthreads();

    const int b = blockIdx.x * NT + tid;
    const float4* __restrict__ xp =
        reinterpret_cast<const float4*>(x + (size_t)b * (TT * II));

    u64 h2[HP];

    for (int t = 0; t < TT; ++t) {
        const float4 xv = __ldg(&xp[t]);
        const u64 x01 = pack2(xv.x, xv.y);
        const u64 x23 = pack2(xv.z, xv.w);

        // refresh packed register copy of h from the thread-private smem column
        #pragma unroll
        for (int kp = 0; kp < HP; ++kp) h2[kp] = hs[kp * NT + tid];

        #pragma unroll 2
        for (int j = 0; j < HH; ++j) {
            const ulonglong2* wr = reinterpret_cast<const ulonglong2*>(sW + (size_t)j * HH);
            const ulonglong2* wz = reinterpret_cast<const ulonglong2*>(sW + (size_t)(j + HH) * HH);
            const ulonglong2* wn = reinterpret_cast<const ulonglong2*>(sW + (size_t)(j + 2 * HH) * HH);

            u64 r0 = 0, r1 = 0, z0 = 0, z1 = 0, n0 = 0, n1 = 0;
            #pragma unroll
            for (int q = 0; q < HP / 2; ++q) {       // 16 iters, 2 pairs each
                const ulonglong2 a = wr[q];
                const ulonglong2 c = wz[q];
                const ulonglong2 d = wn[q];
                const u64 ha = h2[2 * q], hb = h2[2 * q + 1];
                r0 = fma2(a.x, ha, r0);  r1 = fma2(a.y, hb, r1);
                z0 = fma2(c.x, ha, z0);  z1 = fma2(c.y, hb, z1);
                n0 = fma2(d.x, ha, n0);  n1 = fma2(d.y, hb, n1);
            }
            const float hr = hsum2(add2(r0, r1)) + sBhh[j];
            const float hz = hsum2(add2(z0, z1)) + sBhh[j + HH];
            const float hn = hsum2(add2(n0, n1)) + sBhh[j + 2 * HH];

            const ulonglong2 wiR = reinterpret_cast<const ulonglong2*>(sWih)[j];
            const ulonglong2 wiZ = reinterpret_cast<const ulonglong2*>(sWih)[j + HH];
            const ulonglong2 wiN = reinterpret_cast<const ulonglong2*>(sWih)[j + 2 * HH];
            const float xr = hsum2(fma2(wiR.x, x01, mul2(wiR.y, x23))) + sBih[j];
            const float xz = hsum2(fma2(wiZ.x, x01, mul2(wiZ.y, x23))) + sBih[j + HH];
            const float xn = hsum2(fma2(wiN.x, x01, mul2(wiN.y, x23))) + sBih[j + 2 * HH];

            const float rg = sigmoidf_(xr + hr);
            const float zg = sigmoidf_(xz + hz);
            const float ng = tanhf_(xn + rg * hn);

            // update scalar half of the packed smem word
            float* hw = reinterpret_cast<float*>(&hs[(j >> 1) * NT + tid]);
            const float ho = hw[j & 1];
            hw[j & 1] = (1.0f - zg) * ng + zg * ho;
        }
    }

    #pragma unroll
    for (int kp = 0; kp < HP; ++kp) {
        const u64 v = hs[kp * NT + tid];
        float l, h; asm("mov.b64 {%0, %1}, %2;" : "=f"(l), "=f"(h) : "l"(v));
        out[(size_t)b * HH + 2 * kp]     = l;
        out[(size_t)b * HH + 2 * kp + 1] = h;
    }
}

extern "C" void kernel_launch(void* const* d_in, const int* in_sizes, int n_in,
                              void* d_out, int out_size) {
    const float* x    = (const float*)d_in[0];
    const float* w_ih = (const float*)d_in[1];
    const float* w_hh = (const float*)d_in[2];
    const float* b_ih = (const float*)d_in[3];
    const float* b_hh = (const float*)d_in[4];
    float* out = (float*)d_out;

    cudaFuncSetAttribute(gru_kernel, cudaFuncAttributeMaxDynamicSharedMemorySize,
                         SMEM_BYTES);
    gru_kernel<<<NB / NT, NT, SMEM_BYTES>>>(x, w_ih, w_hh, b_ih, b_hh, out);
}

// round 4
// speedup vs baseline: 2.2637x; 2.1005x over previous
#include <cuda_runtime.h>
#include <cuda_bf16.h>
#include <cstdint>

// GRU last-hidden via per-step mma.sync (m16n8k16 bf16) batched GEMM.
// B=16384, T=512, I=4, H=64.  CTA = 128 batch rows, 256 threads, grid = 128.
// Per step: D[128 x 256] = A[128 x 208] @ B[208 x 256], bf16 3-term split.
// N interleaved as n = 4*j + gate, gate in {r, z, hn, xn}  -> epilogue
// stays in registers (2 shfl.xor per tile), h_old register-resident.

#define NB 16384
#define TT 512
#define HH 64
#define NT 256

// smem byte offsets
#define A_HI 0            // 128 rows x 64 bf16 (128B rows, SW128)   16384
#define A_LO 16384        // 16384
#define A_X  32768        // 128 rows x 16 bf16 (32B rows)            4096
#define B_HI 36864        // 256 rows x 64 bf16 (SW128)              32768
#define B_LO 69632        // 32768
#define B_X  102400       // 256 rows x 16 bf16 (32B rows)            8192
#define SMEM_TOTAL 110592

typedef unsigned short u16;

static __device__ __forceinline__ uint32_t smem_u32(const void* p) {
    uint32_t a;
    asm("{ .reg .u64 t; cvta.to.shared.u64 t, %1; cvt.u32.u64 %0, t; }" : "=r"(a) : "l"(p));
    return a;
}
// word = {low half: bf16(even), high half: bf16(odd)}
static __device__ __forceinline__ uint32_t packbf(float even, float odd) {
    uint32_t w;
    asm("cvt.rn.bf16x2.f32 %0, %1, %2;" : "=r"(w) : "f"(odd), "f"(even));
    return w;
}
static __device__ __forceinline__ void st16(uint32_t addr, u16 v) {
    asm volatile("st.shared.b16 [%0], %1;" :: "r"(addr), "h"(v));
}
static __device__ __forceinline__ void st32(uint32_t addr, uint32_t v) {
    asm volatile("st.shared.b32 [%0], %1;" :: "r"(addr), "r"(v));
}
static __device__ __forceinline__ void stv4(uint32_t addr, uint32_t a, uint32_t b,
                                            uint32_t c, uint32_t d) {
    asm volatile("st.shared.v4.b32 [%0], {%1,%2,%3,%4};"
                 :: "r"(addr), "r"(a), "r"(b), "r"(c), "r"(d));
}
static __device__ __forceinline__ void ldm4(uint32_t addr, uint32_t r[4]) {
    asm volatile("ldmatrix.sync.aligned.m8n8.x4.shared.b16 {%0,%1,%2,%3}, [%4];"
                 : "=r"(r[0]), "=r"(r[1]), "=r"(r[2]), "=r"(r[3]) : "r"(addr));
}
static __device__ __forceinline__ void mma_bf16(float d[4], const uint32_t a[4],
                                                const uint32_t b[2]) {
    asm volatile("mma.sync.aligned.m16n8k16.row.col.f32.bf16.bf16.f32 "
                 "{%0,%1,%2,%3}, {%4,%5,%6,%7}, {%8,%9}, {%0,%1,%2,%3};"
                 : "+f"(d[0]), "+f"(d[1]), "+f"(d[2]), "+f"(d[3])
                 : "r"(a[0]), "r"(a[1]), "r"(a[2]), "r"(a[3]), "r"(b[0]), "r"(b[1]));
}
static __device__ __forceinline__ float sigf(float v) {
    return __fdividef(1.0f, 1.0f + __expf(-v));
}
static __device__ __forceinline__ float tanhf_(float v) {
    return 1.0f - __fdividef(2.0f, __expf(2.0f * v) + 1.0f);
}

extern __shared__ char smem_[];

__global__ void __launch_bounds__(NT, 1)
gru_mma_kernel(const float* __restrict__ x,      // [B, T, 4]
               const float* __restrict__ w_ih,   // [192, 4]
               const float* __restrict__ w_hh,   // [192, 64]
               const float* __restrict__ b_ih,   // [192]
               const float* __restrict__ b_hh,   // [192]
               float* __restrict__ out)          // [B, 64]
{
    const uint32_t sb = smem_u32(smem_);
    const int tid  = threadIdx.x;
    const int lane = tid & 31;
    const int wid  = tid >> 5;
    const int mi   = wid & 1;          // M half
    const int nj   = wid >> 1;         // N quarter (16 j's)
    const int mi64 = mi * 64;

    // lane constants
    const uint32_t ar    = (uint32_t)(lane & 15);        // A ldmatrix row-in-tile
    const uint32_t axor  = (uint32_t)(lane & 7) * 16;    // SW128 xor (A and B)
    const uint32_t acolk = (uint32_t)(lane >> 4) * 16;   // A kseg byte offset
    const uint32_t bkseg = (uint32_t)((lane >> 3) & 1) * 16;
    const uint32_t bnrow = (uint32_t)(lane >> 4) * 8 + (uint32_t)(lane & 7);
    const int aa   = lane >> 2;        // 0..7 accumulator row group
    const int oddc = lane & 1;
    const int jsel = (lane >> 1) & 1;
    const uint32_t hxor = (uint32_t)aa * 16;             // h' STS swizzle xor

    // ---- build static B operand + zero A ----
    for (int idx = tid; idx < 256 * 64; idx += NT) {
        const int n = idx >> 6, k = idx & 63;
        const int j = n >> 2, g = n & 3;
        const float v = (g < 3) ? w_hh[(g * 64 + j) * 64 + k] : 0.0f;
        const uint32_t w = packbf(v, v);
        const float fhi = __uint_as_float(w << 16);
        const uint32_t wl = packbf((g < 3) ? (v - fhi) : 0.0f, 0.0f);
        const uint32_t off = (uint32_t)n * 128 + (((uint32_t)k * 2) ^ ((uint32_t)(n & 7) * 16));
        st16(sb + B_HI + off, (u16)w);
        st16(sb + B_LO + off, (u16)wl);
    }
    for (int idx = tid; idx < 256 * 16; idx += NT) {
        const int n = idx >> 4, kk = idx & 15;
        const int j = n >> 2, g = n & 3;
        const int gr = (g == 0) ? j : (g == 1) ? 64 + j : (g == 3) ? 128 + j : -1;
        float full = 0.0f;
        bool want_lo = false;
        if (kk <= 11) {
            if (gr >= 0) full = w_ih[gr * 4 + (kk & 3)];
            want_lo = (kk >= 8);
        } else if (kk <= 13) {
            full = (g == 0) ? b_ih[j] + b_hh[j]
                 : (g == 1) ? b_ih[64 + j] + b_hh[64 + j]
                 : (g == 2) ? b_hh[128 + j]
                            : b_ih[128 + j];
            want_lo = (kk == 13);
        }
        const uint32_t w = packbf(full, full);
        const float fhi = __uint_as_float(w << 16);
        const u16 val = want_lo ? (u16)packbf(full - fhi, 0.0f) : (u16)w;
        st16(sb + B_X + (uint32_t)n * 32 + (uint32_t)kk * 2, val);
    }
    for (int idx = tid; idx < (16384 * 2 + 4096) / 4; idx += NT)
        st32(sb + A_HI + (uint32_t)idx * 4, 0u);

    // initial x (t=0)
    const float4* __restrict__ xp =
        reinterpret_cast<const float4*>(x + (size_t)(blockIdx.x * 128 + tid) * (TT * 4));
    if (tid < 128) {
        const float4 v = __ldg(&xp[0]);
        const uint32_t w0 = packbf(v.x, v.y), w1 = packbf(v.z, v.w);
        const uint32_t w2 = packbf(v.x - __uint_as_float(w0 << 16),
                                   v.y - __uint_as_float(w0 & 0xFFFF0000u));
        const uint32_t w3 = packbf(v.z - __uint_as_float(w1 << 16),
                                   v.w - __uint_as_float(w1 & 0xFFFF0000u));
        const uint32_t ax = sb + A_X + (uint32_t)tid * 32;
        stv4(ax, w0, w1, w2, w3);
        stv4(ax + 16, w0, w1, 0x3F803F80u, 0u);
    }
    __syncthreads();

    float hold[32];
    #pragma unroll
    for (int s = 0; s < 32; ++s) hold[s] = 0.0f;

    for (int t = 0; t < TT; ++t) {
        float4 xn4;
        const bool havex = (tid < 128) && (t + 1 < TT);
        if (havex) xn4 = __ldg(&xp[t + 1]);

        #pragma unroll 1
        for (int nh = 0; nh < 2; ++nh) {
            const uint32_t nbase = (uint32_t)(nj * 64 + nh * 32);
            float d[4][4][4];
            #pragma unroll
            for (int mt = 0; mt < 4; ++mt)
                #pragma unroll
                for (int nt = 0; nt < 4; ++nt)
                    #pragma unroll
                    for (int e = 0; e < 4; ++e) d[mt][nt][e] = 0.0f;

            #pragma unroll
            for (int kt = 0; kt < 13; ++kt) {
                uint32_t af[4][4];
                #pragma unroll
                for (int mt = 0; mt < 4; ++mt) {
                    uint32_t addr;
                    const uint32_t mrow = (uint32_t)(mi64 + mt * 16) + ar;
                    if (kt == 12) {
                        addr = sb + A_X + mrow * 32 + acolk;
                    } else {
                        const uint32_t ab = (kt < 4 || kt >= 8) ? A_HI : A_LO;
                        const uint32_t k4 = (uint32_t)(kt & 3);
                        addr = sb + ab + mrow * 128 + ((k4 * 32 + acolk) ^ axor);
                    }
                    ldm4(addr, af[mt]);
                }
                uint32_t bf[4][2];
                #pragma unroll
                for (int q = 0; q < 2; ++q) {
                    const uint32_t n = nbase + (uint32_t)q * 16 + bnrow;
                    uint32_t addr;
                    if (kt == 12) {
                        addr = sb + B_X + n * 32 + bkseg;
                    } else {
                        const uint32_t bb = (kt < 8) ? B_HI : B_LO;
                        const uint32_t k4 = (uint32_t)(kt & 3);
                        addr = sb + bb + n * 128 + ((k4 * 32 + bkseg) ^ axor);
                    }
                    uint32_t r[4];
                    ldm4(addr, r);
                    bf[2 * q][0] = r[0]; bf[2 * q][1] = r[1];
                    bf[2 * q + 1][0] = r[2]; bf[2 * q + 1][1] = r[3];
                }
                #pragma unroll
                for (int mt = 0; mt < 4; ++mt)
                    #pragma unroll
                    for (int nt = 0; nt < 4; ++nt)
                        mma_bf16(d[mt][nt], af[mt], bf[nt]);
            }

            // epilogue (registers + shfl only)
            #pragma unroll
            for (int mt = 0; mt < 4; ++mt)
                #pragma unroll
                for (int nt = 0; nt < 4; ++nt) {
                    const float* D = d[mt][nt];
                    const float sA = oddc ? D[0] : D[2];
                    const float sB = oddc ? D[1] : D[3];
                    const float pA = __shfl_xor_sync(0xFFFFFFFFu, sA, 1);
                    const float pB = __shfl_xor_sync(0xFFFFFFFFu, sB, 1);
                    const float rp  = oddc ? pA  : D[0];
                    const float zp  = oddc ? pB  : D[1];
                    const float hnp = oddc ? D[2] : pA;
                    const float xnp = oddc ? D[3] : pB;
                    const float r = sigf(rp);
                    const float z = sigf(zp);
                    const float n = tanhf_(xnp + r * hnp);
                    const int s = mt * 8 + nh * 4 + nt;
                    hold[s] = n + z * (hold[s] - n);
                }
        }

        __syncthreads();   // all A reads of this step done

        // write h' (bf16 hi/lo) into A operand for next step
        #pragma unroll
        for (int mt = 0; mt < 4; ++mt)
            #pragma unroll
            for (int s8 = 0; s8 < 8; ++s8) {
                const float h = hold[mt * 8 + s8];
                const uint32_t w = packbf(h, h);
                const uint32_t wl = packbf(h - __uint_as_float(w << 16), 0.0f);
                const uint32_t row = (uint32_t)(mi64 + mt * 16 + aa + 8 * oddc);
                const uint32_t j = (uint32_t)(nj * 16 + s8 * 2 + jsel);
                const uint32_t off = row * 128 + ((j * 2) ^ hxor);
                st16(sb + A_HI + off, (u16)w);
                st16(sb + A_LO + off, (u16)wl);
            }
        if (havex) {
            const uint32_t w0 = packbf(xn4.x, xn4.y), w1 = packbf(xn4.z, xn4.w);
            const uint32_t w2 = packbf(xn4.x - __uint_as_float(w0 << 16),
                                       xn4.y - __uint_as_float(w0 & 0xFFFF0000u));
            const uint32_t w3 = packbf(xn4.z - __uint_as_float(w1 << 16),
                                       xn4.w - __uint_as_float(w1 & 0xFFFF0000u));
            const uint32_t ax = sb + A_X + (uint32_t)tid * 32;
            stv4(ax, w0, w1, w2, w3);
            stv4(ax + 16, w0, w1, 0x3F803F80u, 0u);
        }
        __syncthreads();
    }

    // write final hidden state
    const size_t bbase = (size_t)blockIdx.x * 128;
    #pragma unroll
    for (int mt = 0; mt < 4; ++mt)
        #pragma unroll
        for (int s8 = 0; s8 < 8; ++s8) {
            const int row = mi64 + mt * 16 + aa + 8 * oddc;
            const int j = nj * 16 + s8 * 2 + jsel;
            out[(bbase + row) * HH + j] = hold[mt * 8 + s8];
        }
}

extern "C" void kernel_launch(void* const* d_in, const int* in_sizes, int n_in,
                              void* d_out, int out_size) {
    const float* x    = (const float*)d_in[0];
    const float* w_ih = (const float*)d_in[1];
    const float* w_hh = (const float*)d_in[2];
    const float* b_ih = (const float*)d_in[3];
    const float* b_hh = (const float*)d_in[4];
    float* out = (float*)d_out;

    cudaFuncSetAttribute(gru_mma_kernel, cudaFuncAttributeMaxDynamicSharedMemorySize,
                         SMEM_TOTAL);
    gru_mma_kernel<<<NB / 128, NT, SMEM_TOTAL>>>(x, w_ih, w_hh, b_ih, b_hh, out);
}

// round 5
// speedup vs baseline: 2.2745x; 1.0048x over previous
#include <cuda_runtime.h>
#include <cuda_bf16.h>
#include <cstdint>

// GRU last-hidden via per-step mma.sync (m16n8k16 bf16) batched GEMM.
// B=16384, T=512, I=4, H=64.  CTA = 128 batch rows, 256 threads, grid = 128.
// Two independent 64-row groups (warps 0-3 / 4-7) with private named
// barriers; A operand double-buffered -> ONE barrier per step per group.
// Per step: D[64 x 256] = A[64 x 208] @ B[208 x 256] per group, bf16 3-term
// split. N interleaved n = 4*j + gate (r,z,hn,xn); epilogue in registers.

#define NB 16384
#define TT 512
#define HH 64
#define NT 256

// A ping-pong buffers: each = A_HI(16384) + A_LO(16384) + A_X(4096) = 36864
#define ABUF   36864
#define AOFF_LO 16384
#define AOFF_X  32768
#define B_HI   73728        // 256 rows x 64 bf16 (SW128)   32768
#define B_LO   106496       // 32768
#define B_X    139264       // 256 rows x 16 bf16            8192
#define SMEM_TOTAL 147456

typedef unsigned short u16;

static __device__ __forceinline__ uint32_t smem_u32(const void* p) {
    uint32_t a;
    asm("{ .reg .u64 t; cvta.to.shared.u64 t, %1; cvt.u32.u64 %0, t; }" : "=r"(a) : "l"(p));
    return a;
}
// word = {low half: bf16(even), high half: bf16(odd)}
static __device__ __forceinline__ uint32_t packbf(float even, float odd) {
    uint32_t w;
    asm("cvt.rn.bf16x2.f32 %0, %1, %2;" : "=r"(w) : "f"(odd), "f"(even));
    return w;
}
static __device__ __forceinline__ void st16(uint32_t addr, u16 v) {
    asm volatile("st.shared.b16 [%0], %1;" :: "r"(addr), "h"(v));
}
static __device__ __forceinline__ void st32(uint32_t addr, uint32_t v) {
    asm volatile("st.shared.b32 [%0], %1;" :: "r"(addr), "r"(v));
}
static __device__ __forceinline__ void stv4(uint32_t addr, uint32_t a, uint32_t b,
                                            uint32_t c, uint32_t d) {
    asm volatile("st.shared.v4.b32 [%0], {%1,%2,%3,%4};"
                 :: "r"(addr), "r"(a), "r"(b), "r"(c), "r"(d));
}
static __device__ __forceinline__ void ldm4(uint32_t addr, uint32_t r[4]) {
    asm volatile("ldmatrix.sync.aligned.m8n8.x4.shared.b16 {%0,%1,%2,%3}, [%4];"
                 : "=r"(r[0]), "=r"(r[1]), "=r"(r[2]), "=r"(r[3]) : "r"(addr));
}
static __device__ __forceinline__ void mma_bf16(float d[4], const uint32_t a[4],
                                                const uint32_t b[2]) {
    asm volatile("mma.sync.aligned.m16n8k16.row.col.f32.bf16.bf16.f32 "
                 "{%0,%1,%2,%3}, {%4,%5,%6,%7}, {%8,%9}, {%0,%1,%2,%3};"
                 : "+f"(d[0]), "+f"(d[1]), "+f"(d[2]), "+f"(d[3])
                 : "r"(a[0]), "r"(a[1]), "r"(a[2]), "r"(a[3]), "r"(b[0]), "r"(b[1]));
}
static __device__ __forceinline__ void gbar(int id) {
    asm volatile("bar.sync %0, 128;" :: "r"(id) : "memory");
}
static __device__ __forceinline__ float sigf(float v) {
    return __fdividef(1.0f, 1.0f + __expf(-v));
}
static __device__ __forceinline__ float tanhf_(float v) {
    return 1.0f - __fdividef(2.0f, __expf(2.0f * v) + 1.0f);
}

extern __shared__ char smem_[];

__global__ void __launch_bounds__(NT, 1)
gru_mma_kernel(const float* __restrict__ x,      // [B, T, 4]
               const float* __restrict__ w_ih,   // [192, 4]
               const float* __restrict__ w_hh,   // [192, 64]
               const float* __restrict__ b_ih,   // [192]
               const float* __restrict__ b_hh,   // [192]
               float* __restrict__ out)          // [B, 64]
{
    const uint32_t sb = smem_u32(smem_);
    const int tid  = threadIdx.x;
    const int lane = tid & 31;
    const int wid  = tid >> 5;
    const int grp  = wid >> 2;         // independent 64-row group
    const int nj   = wid & 3;          // N quarter (16 j's)
    const int grow = grp * 64;

    // lane constants
    const uint32_t ar    = (uint32_t)(lane & 15);        // A ldmatrix row-in-tile
    const uint32_t axor  = (uint32_t)(lane & 7) * 16;    // SW128 xor (A and B)
    const uint32_t acolk = (uint32_t)(lane >> 4) * 16;   // A kseg byte offset
    const uint32_t bkseg = (uint32_t)((lane >> 3) & 1) * 16;
    const uint32_t bnrow = (uint32_t)(lane >> 4) * 8 + (uint32_t)(lane & 7);
    const int aa   = lane >> 2;        // 0..7 accumulator row group
    const int oddc = lane & 1;
    const int jsel = (lane >> 1) & 1;
    const uint32_t hxor = (uint32_t)aa * 16;             // h' STS swizzle xor

    // ---- build static B operand ----
    for (int idx = tid; idx < 256 * 64; idx += NT) {
        const int n = idx >> 6, k = idx & 63;
        const int j = n >> 2, g = n & 3;
        const float v = (g < 3) ? w_hh[(g * 64 + j) * 64 + k] : 0.0f;
        const uint32_t w = packbf(v, v);
        const float fhi = __uint_as_float(w << 16);
        const uint32_t wl = packbf((g < 3) ? (v - fhi) : 0.0f, 0.0f);
        const uint32_t off = (uint32_t)n * 128 + (((uint32_t)k * 2) ^ ((uint32_t)(n & 7) * 16));
        st16(sb + B_HI + off, (u16)w);
        st16(sb + B_LO + off, (u16)wl);
    }
    for (int idx = tid; idx < 256 * 16; idx += NT) {
        const int n = idx >> 4, kk = idx & 15;
        const int j = n >> 2, g = n & 3;
        const int gr = (g == 0) ? j : (g == 1) ? 64 + j : (g == 3) ? 128 + j : -1;
        float full = 0.0f;
        bool want_lo = false;
        if (kk <= 11) {
            if (gr >= 0) full = w_ih[gr * 4 + (kk & 3)];
            want_lo = (kk >= 8);
        } else if (kk <= 13) {
            full = (g == 0) ? b_ih[j] + b_hh[j]
                 : (g == 1) ? b_ih[64 + j] + b_hh[64 + j]
                 : (g == 2) ? b_hh[128 + j]
                            : b_ih[128 + j];
            want_lo = (kk == 13);
        }
        const uint32_t w = packbf(full, full);
        const float fhi = __uint_as_float(w << 16);
        const u16 val = want_lo ? (u16)packbf(full - fhi, 0.0f) : (u16)w;
        st16(sb + B_X + (uint32_t)n * 32 + (uint32_t)kk * 2, val);
    }
    // zero both A buffers (73728 bytes)
    for (int idx = tid; idx < (2 * ABUF) / 4; idx += NT)
        st32(sb + (uint32_t)idx * 4, 0u);

    // per-group x loader: local thread lt<64 owns row grow + lt
    const int lt = tid & 127;
    const bool xldr = (lt < 64);
    const int xrow = grow + lt;                       // CTA-local row
    const float4* __restrict__ xp =
        reinterpret_cast<const float4*>(x + (size_t)(blockIdx.x * 128 + xrow) * (TT * 4));

    if (xldr) {   // x(t=0) -> buffer 0
        const float4 v = __ldg(&xp[0]);
        const uint32_t w0 = packbf(v.x, v.y), w1 = packbf(v.z, v.w);
        const uint32_t w2 = packbf(v.x - __uint_as_float(w0 << 16),
                                   v.y - __uint_as_float(w0 & 0xFFFF0000u));
        const uint32_t w3 = packbf(v.z - __uint_as_float(w1 << 16),
                                   v.w - __uint_as_float(w1 & 0xFFFF0000u));
        const uint32_t ax = sb + AOFF_X + (uint32_t)xrow * 32;
        stv4(ax, w0, w1, w2, w3);
        stv4(ax + 16, w0, w1, 0x3F803F80u, 0u);
    }
    __syncthreads();

    float hold[32];
    #pragma unroll
    for (int s = 0; s < 32; ++s) hold[s] = 0.0f;

    for (int t = 0; t < TT; ++t) {
        const uint32_t aR = sb + (uint32_t)(t & 1) * ABUF;        // read buffer
        const uint32_t aW = sb + (uint32_t)((t + 1) & 1) * ABUF;  // write buffer

        float4 xn4;
        const bool havex = xldr && (t + 1 < TT);
        if (havex) xn4 = __ldg(&xp[t + 1]);

        #pragma unroll 1
        for (int nh = 0; nh < 2; ++nh) {
            const uint32_t nbase = (uint32_t)(nj * 64 + nh * 32);
            float d[4][4][4];
            #pragma unroll
            for (int mt = 0; mt < 4; ++mt)
                #pragma unroll
                for (int nt = 0; nt < 4; ++nt)
                    #pragma unroll
                    for (int e = 0; e < 4; ++e) d[mt][nt][e] = 0.0f;

            #pragma unroll
            for (int kt = 0; kt < 13; ++kt) {
                uint32_t af[4][4];
                #pragma unroll
                for (int mt = 0; mt < 4; ++mt) {
                    uint32_t addr;
                    const uint32_t mrow = (uint32_t)(grow + mt * 16) + ar;
                    if (kt == 12) {
                        addr = aR + AOFF_X + mrow * 32 + acolk;
                    } else {
                        const uint32_t ab = (kt < 4 || kt >= 8) ? 0u : AOFF_LO;
                        const uint32_t k4 = (uint32_t)(kt & 3);
                        addr = aR + ab + mrow * 128 + ((k4 * 32 + acolk) ^ axor);
                    }
                    ldm4(addr, af[mt]);
                }
                uint32_t bf[4][2];
                #pragma unroll
                for (int q = 0; q < 2; ++q) {
                    const uint32_t n = nbase + (uint32_t)q * 16 + bnrow;
                    uint32_t addr;
                    if (kt == 12) {
                        addr = sb + B_X + n * 32 + bkseg;
                    } else {
                        const uint32_t bb = (kt < 8) ? B_HI : B_LO;
                        const uint32_t k4 = (uint32_t)(kt & 3);
                        addr = sb + bb + n * 128 + ((k4 * 32 + bkseg) ^ axor);
                    }
                    uint32_t r[4];
                    ldm4(addr, r);
                    bf[2 * q][0] = r[0]; bf[2 * q][1] = r[1];
                    bf[2 * q + 1][0] = r[2]; bf[2 * q + 1][1] = r[3];
                }
                #pragma unroll
                for (int mt = 0; mt < 4; ++mt)
                    #pragma unroll
                    for (int nt = 0; nt < 4; ++nt)
                        mma_bf16(d[mt][nt], af[mt], bf[nt]);
            }

            // epilogue (registers + shfl only)
            #pragma unroll
            for (int mt = 0; mt < 4; ++mt)
                #pragma unroll
                for (int nt = 0; nt < 4; ++nt) {
                    const float* D = d[mt][nt];
                    const float sA = oddc ? D[0] : D[2];
                    const float sB = oddc ? D[1] : D[3];
                    const float pA = __shfl_xor_sync(0xFFFFFFFFu, sA, 1);
                    const float pB = __shfl_xor_sync(0xFFFFFFFFu, sB, 1);
                    const float rp  = oddc ? pA  : D[0];
                    const float zp  = oddc ? pB  : D[1];
                    const float hnp = oddc ? D[2] : pA;
                    const float xnp = oddc ? D[3] : pB;
                    const float r = sigf(rp);
                    const float z = sigf(zp);
                    const float n = tanhf_(xnp + r * hnp);
                    const int s = mt * 8 + nh * 4 + nt;
                    hold[s] = n + z * (hold[s] - n);
                }
        }

        // write h' (bf16 hi/lo) into the NEXT A buffer
        #pragma unroll
        for (int mt = 0; mt < 4; ++mt)
            #pragma unroll
            for (int s8 = 0; s8 < 8; ++s8) {
                const float h = hold[mt * 8 + s8];
                const uint32_t w = packbf(h, h);
                const uint32_t wl = packbf(h - __uint_as_float(w << 16), 0.0f);
                const uint32_t row = (uint32_t)(grow + mt * 16 + aa + 8 * oddc);
                const uint32_t j = (uint32_t)(nj * 16 + s8 * 2 + jsel);
                const uint32_t off = row * 128 + ((j * 2) ^ hxor);
                st16(sb + 0       + (aW - sb) + off, (u16)w);
                st16(sb + AOFF_LO + (aW - sb) + off, (u16)wl);
            }
        if (havex) {
            const uint32_t w0 = packbf(xn4.x, xn4.y), w1 = packbf(xn4.z, xn4.w);
            const uint32_t w2 = packbf(xn4.x - __uint_as_float(w0 << 16),
                                       xn4.y - __uint_as_float(w0 & 0xFFFF0000u));
            const uint32_t w3 = packbf(xn4.z - __uint_as_float(w1 << 16),
                                       xn4.w - __uint_as_float(w1 & 0xFFFF0000u));
            const uint32_t ax = aW + AOFF_X + (uint32_t)xrow * 32;
            stv4(ax, w0, w1, w2, w3);
            stv4(ax + 16, w0, w1, 0x3F803F80u, 0u);
        }
        gbar(grp + 1);   // single per-group barrier per step
    }

    // write final hidden state
    const size_t bbase = (size_t)blockIdx.x * 128;
    #pragma unroll
    for (int mt = 0; mt < 4; ++mt)
        #pragma unroll
        for (int s8 = 0; s8 < 8; ++s8) {
            const int row = grow + mt * 16 + aa + 8 * oddc;
            const int j = nj * 16 + s8 * 2 + jsel;
            out[(bbase + row) * HH + j] = hold[mt * 8 + s8];
        }
}

extern "C" void kernel_launch(void* const* d_in, const int* in_sizes, int n_in,
                              void* d_out, int out_size) {
    const float* x    = (const float*)d_in[0];
    const float* w_ih = (const float*)d_in[1];
    const float* w_hh = (const float*)d_in[2];
    const float* b_ih = (const float*)d_in[3];
    const float* b_hh = (const float*)d_in[4];
    float* out = (float*)d_out;

    cudaFuncSetAttribute(gru_mma_kernel, cudaFuncAttributeMaxDynamicSharedMemorySize,
                         SMEM_TOTAL);
    gru_mma_kernel<<<NB / 128, NT, SMEM_TOTAL>>>(x, w_ih, w_hh, b_ih, b_hh, out);
}

// round 6
// speedup vs baseline: 3.1544x; 1.3869x over previous
#include <cuda_runtime.h>
#include <cuda_bf16.h>
#include <cstdint>

// GRU last-hidden via per-step mma.sync (m16n8k16 bf16) batched GEMM.
// B=16384, T=512, I=4, H=64.  CTA = 128 batch rows, 512 threads, grid = 128.
// FOUR independent 32-row groups (warps 4g..4g+3), each with a private named
// barrier and ping-pong A slice -> 4 warps per SMSP from decoupled chains.
// Per step per group: D[32 x 256] = A[32 x 208] @ B[208 x 256], bf16 3-term
// split. N interleaved n = 4*j + gate (r,z,hn,xn); epilogue in registers.

#define NB 16384
#define TT 512
#define HH 64
#define NT 512

// A ping-pong buffers: each = A_HI(16384) + A_LO(16384) + A_X(4096) = 36864
#define ABUF   36864
#define AOFF_LO 16384
#define AOFF_X  32768
#define B_HI   73728        // 256 rows x 64 bf16 (SW128)   32768
#define B_LO   106496       // 32768
#define B_X    139264       // 256 rows x 16 bf16            8192
#define SMEM_TOTAL 147456

typedef unsigned short u16;

static __device__ __forceinline__ uint32_t smem_u32(const void* p) {
    uint32_t a;
    asm("{ .reg .u64 t; cvta.to.shared.u64 t, %1; cvt.u32.u64 %0, t; }" : "=r"(a) : "l"(p));
    return a;
}
// word = {low half: bf16(even), high half: bf16(odd)}
static __device__ __forceinline__ uint32_t packbf(float even, float odd) {
    uint32_t w;
    asm("cvt.rn.bf16x2.f32 %0, %1, %2;" : "=r"(w) : "f"(odd), "f"(even));
    return w;
}
static __device__ __forceinline__ void st16(uint32_t addr, u16 v) {
    asm volatile("st.shared.b16 [%0], %1;" :: "r"(addr), "h"(v));
}
static __device__ __forceinline__ void st32(uint32_t addr, uint32_t v) {
    asm volatile("st.shared.b32 [%0], %1;" :: "r"(addr), "r"(v));
}
static __device__ __forceinline__ void stv4(uint32_t addr, uint32_t a, uint32_t b,
                                            uint32_t c, uint32_t d) {
    asm volatile("st.shared.v4.b32 [%0], {%1,%2,%3,%4};"
                 :: "r"(addr), "r"(a), "r"(b), "r"(c), "r"(d));
}
static __device__ __forceinline__ void ldm4(uint32_t addr, uint32_t r[4]) {
    asm volatile("ldmatrix.sync.aligned.m8n8.x4.shared.b16 {%0,%1,%2,%3}, [%4];"
                 : "=r"(r[0]), "=r"(r[1]), "=r"(r[2]), "=r"(r[3]) : "r"(addr));
}
static __device__ __forceinline__ void mma_bf16(float d[4], const uint32_t a[4],
                                                const uint32_t b[2]) {
    asm volatile("mma.sync.aligned.m16n8k16.row.col.f32.bf16.bf16.f32 "
                 "{%0,%1,%2,%3}, {%4,%5,%6,%7}, {%8,%9}, {%0,%1,%2,%3};"
                 : "+f"(d[0]), "+f"(d[1]), "+f"(d[2]), "+f"(d[3])
                 : "r"(a[0]), "r"(a[1]), "r"(a[2]), "r"(a[3]), "r"(b[0]), "r"(b[1]));
}
static __device__ __forceinline__ void gbar(int id) {
    asm volatile("bar.sync %0, 128;" :: "r"(id) : "memory");
}
static __device__ __forceinline__ float sigf(float v) {
    return __fdividef(1.0f, 1.0f + __expf(-v));
}
static __device__ __forceinline__ float tanhf_(float v) {
    return 1.0f - __fdividef(2.0f, __expf(2.0f * v) + 1.0f);
}

extern __shared__ char smem_[];

__global__ void __launch_bounds__(NT, 1)
gru_mma_kernel(const float* __restrict__ x,      // [B, T, 4]
               const float* __restrict__ w_ih,   // [192, 4]
               const float* __restrict__ w_hh,   // [192, 64]
               const float* __restrict__ b_ih,   // [192]
               const float* __restrict__ b_hh,   // [192]
               float* __restrict__ out)          // [B, 64]
{
    const uint32_t sb = smem_u32(smem_);
    const int tid  = threadIdx.x;
    const int lane = tid & 31;
    const int wid  = tid >> 5;
    const int grp  = wid >> 2;         // independent 32-row group (0..3)
    const int nj   = wid & 3;          // N quarter (16 j's)
    const int grow = grp * 32;

    // lane constants
    const uint32_t ar    = (uint32_t)(lane & 15);        // A ldmatrix row-in-tile
    const uint32_t axor  = (uint32_t)(lane & 7) * 16;    // SW128 xor (A and B)
    const uint32_t acolk = (uint32_t)(lane >> 4) * 16;   // A kseg byte offset
    const uint32_t bkseg = (uint32_t)((lane >> 3) & 1) * 16;
    const uint32_t bnrow = (uint32_t)(lane >> 4) * 8 + (uint32_t)(lane & 7);
    const int aa   = lane >> 2;        // 0..7 accumulator row group
    const int oddc = lane & 1;
    const int jsel = (lane >> 1) & 1;
    const uint32_t hxor = (uint32_t)aa * 16;             // h' STS swizzle xor

    // ---- build static B operand ----
    for (int idx = tid; idx < 256 * 64; idx += NT) {
        const int n = idx >> 6, k = idx & 63;
        const int j = n >> 2, g = n & 3;
        const float v = (g < 3) ? w_hh[(g * 64 + j) * 64 + k] : 0.0f;
        const uint32_t w = packbf(v, v);
        const float fhi = __uint_as_float(w << 16);
        const uint32_t wl = packbf((g < 3) ? (v - fhi) : 0.0f, 0.0f);
        const uint32_t off = (uint32_t)n * 128 + (((uint32_t)k * 2) ^ ((uint32_t)(n & 7) * 16));
        st16(sb + B_HI + off, (u16)w);
        st16(sb + B_LO + off, (u16)wl);
    }
    for (int idx = tid; idx < 256 * 16; idx += NT) {
        const int n = idx >> 4, kk = idx & 15;
        const int j = n >> 2, g = n & 3;
        const int gr = (g == 0) ? j : (g == 1) ? 64 + j : (g == 3) ? 128 + j : -1;
        float full = 0.0f;
        bool want_lo = false;
        if (kk <= 11) {
            if (gr >= 0) full = w_ih[gr * 4 + (kk & 3)];
            want_lo = (kk >= 8);
        } else if (kk <= 13) {
            full = (g == 0) ? b_ih[j] + b_hh[j]
                 : (g == 1) ? b_ih[64 + j] + b_hh[64 + j]
                 : (g == 2) ? b_hh[128 + j]
                            : b_ih[128 + j];
            want_lo = (kk == 13);
        }
        const uint32_t w = packbf(full, full);
        const float fhi = __uint_as_float(w << 16);
        const u16 val = want_lo ? (u16)packbf(full - fhi, 0.0f) : (u16)w;
        st16(sb + B_X + (uint32_t)n * 32 + (uint32_t)kk * 2, val);
    }
    // zero both A buffers (73728 bytes)
    for (int idx = tid; idx < (2 * ABUF) / 4; idx += NT)
        st32(sb + (uint32_t)idx * 4, 0u);

    // per-group x loader: local thread lt<32 owns row grow + lt
    const int lt = tid & 127;
    const bool xldr = (lt < 32);
    const int xrow = grow + lt;                       // CTA-local row
    const float4* __restrict__ xp =
        reinterpret_cast<const float4*>(x + (size_t)(blockIdx.x * 128 + xrow) * (TT * 4));

    if (xldr) {   // x(t=0) -> buffer 0
        const float4 v = __ldg(&xp[0]);
        const uint32_t w0 = packbf(v.x, v.y), w1 = packbf(v.z, v.w);
        const uint32_t w2 = packbf(v.x - __uint_as_float(w0 << 16),
                                   v.y - __uint_as_float(w0 & 0xFFFF0000u));
        const uint32_t w3 = packbf(v.z - __uint_as_float(w1 << 16),
                                   v.w - __uint_as_float(w1 & 0xFFFF0000u));
        const uint32_t ax = sb + AOFF_X + (uint32_t)xrow * 32;
        stv4(ax, w0, w1, w2, w3);
        stv4(ax + 16, w0, w1, 0x3F803F80u, 0u);
    }
    __syncthreads();

    float hold[16];
    #pragma unroll
    for (int s = 0; s < 16; ++s) hold[s] = 0.0f;

    for (int t = 0; t < TT; ++t) {
        const uint32_t aR = sb + (uint32_t)(t & 1) * ABUF;        // read buffer
        const uint32_t aW = sb + (uint32_t)((t + 1) & 1) * ABUF;  // write buffer

        float4 xn4;
        const bool havex = xldr && (t + 1 < TT);
        if (havex) xn4 = __ldg(&xp[t + 1]);

        #pragma unroll 1
        for (int nh = 0; nh < 2; ++nh) {
            const uint32_t nbase = (uint32_t)(nj * 64 + nh * 32);
            float d[2][4][4];
            #pragma unroll
            for (int mt = 0; mt < 2; ++mt)
                #pragma unroll
                for (int nt = 0; nt < 4; ++nt)
                    #pragma unroll
                    for (int e = 0; e < 4; ++e) d[mt][nt][e] = 0.0f;

            #pragma unroll
            for (int kt = 0; kt < 13; ++kt) {
                uint32_t af[2][4];
                #pragma unroll
                for (int mt = 0; mt < 2; ++mt) {
                    uint32_t addr;
                    const uint32_t mrow = (uint32_t)(grow + mt * 16) + ar;
                    if (kt == 12) {
                        addr = aR + AOFF_X + mrow * 32 + acolk;
                    } else {
                        const uint32_t ab = (kt < 4 || kt >= 8) ? 0u : AOFF_LO;
                        const uint32_t k4 = (uint32_t)(kt & 3);
                        addr = aR + ab + mrow * 128 + ((k4 * 32 + acolk) ^ axor);
                    }
                    ldm4(addr, af[mt]);
                }
                uint32_t bf[4][2];
                #pragma unroll
                for (int q = 0; q < 2; ++q) {
                    const uint32_t n = nbase + (uint32_t)q * 16 + bnrow;
                    uint32_t addr;
                    if (kt == 12) {
                        addr = sb + B_X + n * 32 + bkseg;
                    } else {
                        const uint32_t bb = (kt < 8) ? B_HI : B_LO;
                        const uint32_t k4 = (uint32_t)(kt & 3);
                        addr = sb + bb + n * 128 + ((k4 * 32 + bkseg) ^ axor);
                    }
                    uint32_t r[4];
                    ldm4(addr, r);
                    bf[2 * q][0] = r[0]; bf[2 * q][1] = r[1];
                    bf[2 * q + 1][0] = r[2]; bf[2 * q + 1][1] = r[3];
                }
                #pragma unroll
                for (int mt = 0; mt < 2; ++mt)
                    #pragma unroll
                    for (int nt = 0; nt < 4; ++nt)
                        mma_bf16(d[mt][nt], af[mt], bf[nt]);
            }

            // epilogue (registers + shfl only)
            #pragma unroll
            for (int mt = 0; mt < 2; ++mt)
                #pragma unroll
                for (int nt = 0; nt < 4; ++nt) {
                    const float* D = d[mt][nt];
                    const float sA = oddc ? D[0] : D[2];
                    const float sB = oddc ? D[1] : D[3];
                    const float pA = __shfl_xor_sync(0xFFFFFFFFu, sA, 1);
                    const float pB = __shfl_xor_sync(0xFFFFFFFFu, sB, 1);
                    const float rp  = oddc ? pA  : D[0];
                    const float zp  = oddc ? pB  : D[1];
                    const float hnp = oddc ? D[2] : pA;
                    const float xnp = oddc ? D[3] : pB;
                    const float r = sigf(rp);
                    const float z = sigf(zp);
                    const float n = tanhf_(xnp + r * hnp);
                    const int s = mt * 8 + nh * 4 + nt;
                    hold[s] = n + z * (hold[s] - n);
                }
        }

        // write h' (bf16 hi/lo) into the NEXT A buffer
        #pragma unroll
        for (int mt = 0; mt < 2; ++mt)
            #pragma unroll
            for (int s8 = 0; s8 < 8; ++s8) {
                const float h = hold[mt * 8 + s8];
                const uint32_t w = packbf(h, h);
                const uint32_t wl = packbf(h - __uint_as_float(w << 16), 0.0f);
                const uint32_t row = (uint32_t)(grow + mt * 16 + aa + 8 * oddc);
                const uint32_t j = (uint32_t)(nj * 16 + s8 * 2 + jsel);
                const uint32_t off = row * 128 + ((j * 2) ^ hxor);
                st16(aW + 0       + off, (u16)w);
                st16(aW + AOFF_LO + off, (u16)wl);
            }
        if (havex) {
            const uint32_t w0 = packbf(xn4.x, xn4.y), w1 = packbf(xn4.z, xn4.w);
            const uint32_t w2 = packbf(xn4.x - __uint_as_float(w0 << 16),
                                       xn4.y - __uint_as_float(w0 & 0xFFFF0000u));
            const uint32_t w3 = packbf(xn4.z - __uint_as_float(w1 << 16),
                                       xn4.w - __uint_as_float(w1 & 0xFFFF0000u));
            const uint32_t ax = aW + AOFF_X + (uint32_t)xrow * 32;
            stv4(ax, w0, w1, w2, w3);
            stv4(ax + 16, w0, w1, 0x3F803F80u, 0u);
        }
        gbar(grp + 1);   // single per-group barrier per step
    }

    // write final hidden state
    const size_t bbase = (size_t)blockIdx.x * 128;
    #pragma unroll
    for (int mt = 0; mt < 2; ++mt)
        #pragma unroll
        for (int s8 = 0; s8 < 8; ++s8) {
            const int row = grow + mt * 16 + aa + 8 * oddc;
            const int j = nj * 16 + s8 * 2 + jsel;
            out[(bbase + row) * HH + j] = hold[mt * 8 + s8];
        }
}

extern "C" void kernel_launch(void* const* d_in, const int* in_sizes, int n_in,
                              void* d_out, int out_size) {
    const float* x    = (const float*)d_in[0];
    const float* w_ih = (const float*)d_in[1];
    const float* w_hh = (const float*)d_in[2];
    const float* b_ih = (const float*)d_in[3];
    const float* b_hh = (const float*)d_in[4];
    float* out = (float*)d_out;

    cudaFuncSetAttribute(gru_mma_kernel, cudaFuncAttributeMaxDynamicSharedMemorySize,
                         SMEM_TOTAL);
    gru_mma_kernel<<<NB / 128, NT, SMEM_TOTAL>>>(x, w_ih, w_hh, b_ih, b_hh, out);
}